// round 15
// baseline (speedup 1.0000x reference)
#include <cuda_runtime.h>
#include <cstdint>

#define B_ 2
#define H_ 16
#define L_ 2048
#define D_ 64
#define BH_ (B_*H_)
#define NC_ 32            // chunks per bh (chunk = 64 rows)
#define EPS_ 1e-6f

typedef unsigned long long u64;

// Scratch (device globals; allocation-free rule).
__device__ float g_kf[(size_t)BH_ * L_ * D_];            // relu(K @ Wk)
__device__ float g_kv[(size_t)BH_ * NC_ * D_ * D_];      // per-chunk Kf^T V
__device__ float g_state[(size_t)BH_ * NC_ * D_ * D_];   // exclusive prefix of g_kv
__device__ float g_ks[(size_t)BH_ * NC_ * D_];           // per-chunk sum of kf
__device__ float g_zs[(size_t)BH_ * NC_ * D_];           // exclusive prefix of g_ks

// ---- packed f32x2 helpers (Blackwell FFMA2 path; used in fmap) ----
__device__ __forceinline__ u64 pk2(float lo, float hi) {
    u64 r; asm("mov.b64 %0, {%1, %2};" : "=l"(r) : "f"(lo), "f"(hi)); return r;
}
__device__ __forceinline__ u64 dup2(float x) {
    u64 r; asm("mov.b64 %0, {%1, %1};" : "=l"(r) : "f"(x)); return r;
}
__device__ __forceinline__ void fma2(u64& d, u64 a, u64 b) {
    asm("fma.rn.f32x2 %0, %1, %2, %0;" : "+l"(d) : "l"(a), "l"(b));
}
__device__ __forceinline__ float2 up2(u64 v) {
    float lo, hi; asm("mov.b64 {%0, %1}, %2;" : "=f"(lo), "=f"(hi) : "l"(v));
    return make_float2(lo, hi);
}

// ===========================================================================
// Key-path feature map + per-chunk KV/ksum.  128 rows per block.
// Grid (L/128, BH); 256 threads; 8x4 micro-tiles; FFMA2; main unroll 8,
// KV unroll 4.  (round-13 exact, measured 36.5us)
// ===========================================================================
#define FM_SMEM 69632

__global__ __launch_bounds__(256)
void fmap_kernel(const float* __restrict__ K, const float* __restrict__ V,
                 const float* __restrict__ Wk)
{
    extern __shared__ float sm[];
    float (*XT)[136] = (float(*)[136])sm;
    float (*Ws)[68]  = (float(*)[68])(sm + 64 * 136);

    const int tile = blockIdx.x, bh = blockIdx.y;
    const int h = bh & (H_ - 1);

    const int tid = threadIdx.x;
    const int row4 = tid >> 2, d0 = (tid & 3) << 4;
    const size_t rowbase = (size_t)bh * L_ + (size_t)tile * 128;

    #pragma unroll
    for (int rr = 0; rr < 128; rr += 64) {
        const float* src = K + (rowbase + rr + row4) * D_ + d0;
        #pragma unroll
        for (int i = 0; i < 4; i++) {
            float4 v = *(const float4*)(src + i * 4);
            XT[d0 + i*4 + 0][rr + row4] = v.x; XT[d0 + i*4 + 1][rr + row4] = v.y;
            XT[d0 + i*4 + 2][rr + row4] = v.z; XT[d0 + i*4 + 3][rr + row4] = v.w;
        }
    }
    {
        const float* wsrc = Wk + (size_t)h * D_ * D_ + (size_t)row4 * D_ + d0;
        #pragma unroll
        for (int i = 0; i < 4; i++)
            *(float4*)&Ws[row4][d0 + i*4] = *(const float4*)(wsrc + i * 4);
    }
    __syncthreads();

    const int ty = tid >> 4, tx = tid & 15;
    u64 acc2[4][4] = {};
    #pragma unroll 8
    for (int d = 0; d < 64; d++) {
        float4 a0 = *(const float4*)&XT[d][ty * 8];
        float4 a1 = *(const float4*)&XT[d][ty * 8 + 4];
        float4 b  = *(const float4*)&Ws[d][tx * 4];
        u64 pa[4] = {pk2(a0.x, a0.y), pk2(a0.z, a0.w),
                     pk2(a1.x, a1.y), pk2(a1.z, a1.w)};
        u64 db[4] = {dup2(b.x), dup2(b.y), dup2(b.z), dup2(b.w)};
        #pragma unroll
        for (int p = 0; p < 4; p++)
            #pragma unroll
            for (int c = 0; c < 4; c++)
                fma2(acc2[p][c], pa[p], db[c]);
    }
    float acc[8][4];
    #pragma unroll
    for (int p = 0; p < 4; p++)
        #pragma unroll
        for (int c = 0; c < 4; c++) {
            float2 v = up2(acc2[p][c]);
            acc[2*p + 0][c] = fmaxf(v.x, 0.f);
            acc[2*p + 1][c] = fmaxf(v.y, 0.f);
        }

    {
        float* dst = g_kf + (rowbase + ty * 8) * D_ + tx * 4;
        #pragma unroll
        for (int r = 0; r < 8; r++)
            *(float4*)(dst + (size_t)r * D_) =
                make_float4(acc[r][0], acc[r][1], acc[r][2], acc[r][3]);
    }

    __syncthreads();
    float (*Ks)[68]  = (float(*)[68])sm;
    float (*Vs2)[68] = (float(*)[68])(sm + 128 * 68);

    #pragma unroll
    for (int r = 0; r < 8; r++)
        *(float4*)&Ks[ty * 8 + r][tx * 4] =
            make_float4(acc[r][0], acc[r][1], acc[r][2], acc[r][3]);
    #pragma unroll
    for (int rr = 0; rr < 128; rr += 64) {
        const float* vs = V + (rowbase + rr + row4) * D_ + d0;
        #pragma unroll
        for (int i = 0; i < 4; i++)
            *(float4*)&Vs2[rr + row4][d0 + i*4] = *(const float4*)(vs + i * 4);
    }
    __syncthreads();

    const int chunk = ty >> 3, tyc = ty & 7;
    const int nbase = chunk * 64;
    u64 kv2[4][4] = {};
    #pragma unroll 4
    for (int n = 0; n < 64; n++) {
        float4 a0 = *(const float4*)&Ks[nbase + n][tyc * 8];
        float4 a1 = *(const float4*)&Ks[nbase + n][tyc * 8 + 4];
        float4 b  = *(const float4*)&Vs2[nbase + n][tx * 4];
        u64 pa[4] = {pk2(a0.x, a0.y), pk2(a0.z, a0.w),
                     pk2(a1.x, a1.y), pk2(a1.z, a1.w)};
        u64 db[4] = {dup2(b.x), dup2(b.y), dup2(b.z), dup2(b.w)};
        #pragma unroll
        for (int p = 0; p < 4; p++)
            #pragma unroll
            for (int c = 0; c < 4; c++)
                fma2(kv2[p][c], pa[p], db[c]);
    }
    {
        float* kvdst = g_kv + ((size_t)(bh * NC_ + tile * 2 + chunk) * D_
                               + tyc * 8) * D_ + tx * 4;
        #pragma unroll
        for (int p = 0; p < 4; p++) {
            float2 v0 = up2(kv2[p][0]), v1 = up2(kv2[p][1]);
            float2 v2 = up2(kv2[p][2]), v3 = up2(kv2[p][3]);
            *(float4*)(kvdst + (size_t)(2*p) * D_)     = make_float4(v0.x, v1.x, v2.x, v3.x);
            *(float4*)(kvdst + (size_t)(2*p + 1) * D_) = make_float4(v0.y, v1.y, v2.y, v3.y);
        }
    }
    if (tid < 128) {
        const int c2 = tid >> 6, d = tid & 63;
        float s = 0.f;
        #pragma unroll 8
        for (int n = 0; n < 64; n++) s += Ks[c2 * 64 + n][d];
        g_ks[(size_t)(bh * NC_ + tile * 2 + c2) * D_ + d] = s;
    }
}

// ===========================================================================
// Exclusive prefix scan, latency-split: 4 lanes per float4 element, each
// owning 8 chunks. Pass 1: segment sums (8 independent loads). shfl_up gives
// cross-segment exclusive offsets. Pass 2: write prefixes (2nd read hits L2).
// Grid (17, BH): g<16 -> 64 float4 elements each; g==16 -> z scan.
// ===========================================================================
__device__ __forceinline__ float4 f4add(float4 a, float4 b) {
    return make_float4(a.x + b.x, a.y + b.y, a.z + b.z, a.w + b.w);
}
__device__ __forceinline__ float4 shfl_up4(float4 v, int d) {
    float4 r;
    r.x = __shfl_up_sync(0xffffffffu, v.x, d);
    r.y = __shfl_up_sync(0xffffffffu, v.y, d);
    r.z = __shfl_up_sync(0xffffffffu, v.z, d);
    r.w = __shfl_up_sync(0xffffffffu, v.w, d);
    return r;
}

__global__ __launch_bounds__(256)
void scan_kernel()
{
    const int g = blockIdx.x, bh = blockIdx.y, tid = threadIdx.x;
    const int seg = tid & 3;          // 4 lanes per element, 8 chunks each
    const int c0 = seg * 8;

    if (g < 16) {
        const int e4 = g * 64 + (tid >> 2);          // float4 idx 0..1023
        const size_t base = (size_t)bh * NC_ * (D_ * D_ / 4) + e4;

        float4 loc = make_float4(0.f, 0.f, 0.f, 0.f);
        #pragma unroll
        for (int j = 0; j < 8; j++)
            loc = f4add(loc, ((const float4*)g_kv)[base + (size_t)(c0 + j) * (D_ * D_ / 4)]);

        float4 o1 = shfl_up4(loc, 1);
        float4 o2 = shfl_up4(loc, 2);
        float4 o3 = shfl_up4(loc, 3);
        float4 acc = make_float4(0.f, 0.f, 0.f, 0.f);
        if (seg >= 1) acc = f4add(acc, o1);
        if (seg >= 2) acc = f4add(acc, o2);
        if (seg >= 3) acc = f4add(acc, o3);

        #pragma unroll
        for (int j = 0; j < 8; j++) {
            const size_t idx = base + (size_t)(c0 + j) * (D_ * D_ / 4);
            ((float4*)g_state)[idx] = acc;
            acc = f4add(acc, ((const float4*)g_kv)[idx]);
        }
    } else if (tid < 64) {
        const int e4 = tid >> 2;                      // float4 idx 0..15
        const size_t base = (size_t)bh * NC_ * (D_ / 4) + e4;

        float4 loc = make_float4(0.f, 0.f, 0.f, 0.f);
        #pragma unroll
        for (int j = 0; j < 8; j++)
            loc = f4add(loc, ((const float4*)g_ks)[base + (size_t)(c0 + j) * (D_ / 4)]);

        float4 o1 = shfl_up4(loc, 1);
        float4 o2 = shfl_up4(loc, 2);
        float4 o3 = shfl_up4(loc, 3);
        float4 acc = make_float4(0.f, 0.f, 0.f, 0.f);
        if (seg >= 1) acc = f4add(acc, o1);
        if (seg >= 2) acc = f4add(acc, o2);
        if (seg >= 3) acc = f4add(acc, o3);

        #pragma unroll
        for (int j = 0; j < 8; j++) {
            const size_t idx = base + (size_t)(c0 + j) * (D_ / 4);
            ((float4*)g_zs)[idx] = acc;
            acc = f4add(acc, ((const float4*)g_ks)[idx]);
        }
    }
}

// ===========================================================================
// Per-chunk output, 3 smem buffers, FUSED GEMM1+GEMM3 (round-10/13, best).
// ===========================================================================
#define OUT_SMEM ((3 * 64 * 68 + 192) * 4)   // 52992 B

__global__ __launch_bounds__(256, 4)
void out_kernel(const float* __restrict__ Q, const float* __restrict__ Wq,
                const float* __restrict__ V, float* __restrict__ Out)
{
    extern __shared__ float sm[];
    float (*bufA)[68] = (float(*)[68])(sm);                 // Wq -> state -> V
    float (*bufB)[68] = (float(*)[68])(sm + 1 * 64 * 68);   // Q^T -> qT[e][m]
    float (*bufC)[68] = (float(*)[68])(sm + 2 * 64 * 68);   // kT[e][n] -> St[n][m]
    float* rowsum     = sm + 3 * 64 * 68;                   // [64]
    float* qz         = rowsum + 64;                        // [64]
    float* zs         = qz + 64;                            // [64]

    const int c = blockIdx.x, bh = blockIdx.y;
    const int h = bh & (H_ - 1);
    const int tid = threadIdx.x;
    const int ty = tid >> 4, tx = tid & 15;
    const size_t rowbase = (size_t)bh * L_ + (size_t)c * 64;
    const size_t chunk = (size_t)(bh * NC_ + c);
    const int row = tid >> 2, d0 = (tid & 3) << 4;

    // ---- 1: load Wq->A, Q^T->B, kf^T->C ----
    {
        const float* ws = Wq + (size_t)h * D_ * D_ + (size_t)row * D_ + d0;
        const float* qs = Q + (rowbase + row) * D_ + d0;
        const float* ks = g_kf + (rowbase + row) * D_ + d0;
        #pragma unroll
        for (int i = 0; i < 4; i++) {
            *(float4*)&bufA[row][d0 + i*4] = *(const float4*)(ws + i * 4);
            float4 q4 = *(const float4*)(qs + i * 4);
            bufB[d0 + i*4 + 0][row] = q4.x; bufB[d0 + i*4 + 1][row] = q4.y;
            bufB[d0 + i*4 + 2][row] = q4.z; bufB[d0 + i*4 + 3][row] = q4.w;
            float4 k4 = *(const float4*)(ks + i * 4);
            bufC[d0 + i*4 + 0][row] = k4.x; bufC[d0 + i*4 + 1][row] = k4.y;
            bufC[d0 + i*4 + 2][row] = k4.z; bufC[d0 + i*4 + 3][row] = k4.w;
        }
        if (tid < 64) zs[tid] = g_zs[chunk * D_ + tid];
    }
    __syncthreads();

    // ---- 2: GEMM0 qf^T = relu(Wq^T Q^T) ----
    float qt[4][4] = {};
    #pragma unroll 8
    for (int d = 0; d < 64; d++) {
        float4 a = *(const float4*)&bufA[d][ty * 4];
        float4 b = *(const float4*)&bufB[d][tx * 4];
        float av[4] = {a.x, a.y, a.z, a.w};
        float bv[4] = {b.x, b.y, b.z, b.w};
        #pragma unroll
        for (int r = 0; r < 4; r++)
            #pragma unroll
            for (int cc = 0; cc < 4; cc++)
                qt[r][cc] = fmaf(av[r], bv[cc], qt[r][cc]);
    }
    #pragma unroll
    for (int r = 0; r < 4; r++)
        #pragma unroll
        for (int cc = 0; cc < 4; cc++)
            qt[r][cc] = fmaxf(qt[r][cc], 0.f);
    __syncthreads();   // A/B reads done

    // ---- 3: qT -> B ; state -> A ----
    float (*qT)[68] = bufB;    // qT[e][m]
    #pragma unroll
    for (int r = 0; r < 4; r++)
        *(float4*)&qT[ty * 4 + r][tx * 4] =
            make_float4(qt[r][0], qt[r][1], qt[r][2], qt[r][3]);
    float (*Sts)[68] = bufA;   // state[d][e]
    {
        const float* ss = g_state + (chunk * D_ + row) * D_ + d0;
        #pragma unroll
        for (int i = 0; i < 4; i++)
            *(float4*)&Sts[row][d0 + i*4] = *(const float4*)(ss + i * 4);
    }
    __syncthreads();

    // ---- 4: FUSED GEMM1+GEMM3: shared a = qT[d][ty*4] ----
    float s[4][4] = {};
    float o[4][4] = {};
    #pragma unroll 4
    for (int d = 0; d < 64; d++) {
        float4 a  = *(const float4*)&qT[d][ty * 4];
        float4 b1 = *(const float4*)&bufC[d][tx * 4];
        float4 b2 = *(const float4*)&Sts[d][tx * 4];
        float av[4]  = {a.x, a.y, a.z, a.w};
        float bv1[4] = {b1.x, b1.y, b1.z, b1.w};
        float bv2[4] = {b2.x, b2.y, b2.z, b2.w};
        #pragma unroll
        for (int r = 0; r < 4; r++)
            #pragma unroll
            for (int cc = 0; cc < 4; cc++) {
                s[r][cc] = fmaf(av[r], bv1[cc], s[r][cc]);
                o[r][cc] = fmaf(av[r], bv2[cc], o[r][cc]);
            }
    }
    #pragma unroll
    for (int r = 0; r < 4; r++)
        #pragma unroll
        for (int cc = 0; cc < 4; cc++)
            if (tx * 4 + cc > ty * 4 + r) s[r][cc] = 0.f;   // causal within chunk

    #pragma unroll
    for (int r = 0; r < 4; r++) {
        float p = (s[r][0] + s[r][1]) + (s[r][2] + s[r][3]);
        p += __shfl_xor_sync(0xffffffffu, p, 1);
        p += __shfl_xor_sync(0xffffffffu, p, 2);
        p += __shfl_xor_sync(0xffffffffu, p, 4);
        p += __shfl_xor_sync(0xffffffffu, p, 8);
        if (tx == 0) rowsum[ty * 4 + r] = p;
    }
    if (tid < 64) {   // qz[m] = qf[m] . z_prev
        float acc = 0.f;
        #pragma unroll 8
        for (int d = 0; d < 64; d++) acc = fmaf(qT[d][tid], zs[d], acc);
        qz[tid] = acc;
    }
    __syncthreads();   // C (kT) + A (state) reads done

    // ---- 5: S^T -> C ; V -> A ----
    float (*St)[68] = bufC;   // St[n][m]
    #pragma unroll
    for (int cc = 0; cc < 4; cc++)
        *(float4*)&St[tx * 4 + cc][ty * 4] =
            make_float4(s[0][cc], s[1][cc], s[2][cc], s[3][cc]);
    float (*Vs)[68] = bufA;   // V[n][dv]
    {
        const float* vs = V + (rowbase + row) * D_ + d0;
        #pragma unroll
        for (int i = 0; i < 4; i++)
            *(float4*)&Vs[row][d0 + i*4] = *(const float4*)(vs + i * 4);
    }
    __syncthreads();

    // ---- 6: GEMM2 O += S @ V (causal bound: warp w rows <= 8w+7 -> n < 8w+8)
    const int nmax = ((tid >> 5) << 3) + 8;
    #pragma unroll 4
    for (int n = 0; n < nmax; n++) {
        float4 a = *(const float4*)&St[n][ty * 4];
        float4 b = *(const float4*)&Vs[n][tx * 4];
        float av[4] = {a.x, a.y, a.z, a.w};
        float bv[4] = {b.x, b.y, b.z, b.w};
        #pragma unroll
        for (int r = 0; r < 4; r++)
            #pragma unroll
            for (int cc = 0; cc < 4; cc++)
                o[r][cc] = fmaf(av[r], bv[cc], o[r][cc]);
    }

    float* dst = Out + (rowbase + ty * 4) * D_ + tx * 4;
    #pragma unroll
    for (int r = 0; r < 4; r++) {
        const float inv = 1.0f / (rowsum[ty * 4 + r] + qz[ty * 4 + r] + EPS_);
        *(float4*)(dst + (size_t)r * D_) =
            make_float4(o[r][0] * inv, o[r][1] * inv, o[r][2] * inv, o[r][3] * inv);
    }
}

// ===========================================================================
extern "C" void kernel_launch(void* const* d_in, const int* in_sizes, int n_in,
                              void* d_out, int out_size)
{
    (void)in_sizes; (void)n_in; (void)out_size;
    const float* Q  = (const float*)d_in[0];
    const float* K  = (const float*)d_in[1];
    const float* V  = (const float*)d_in[2];
    const float* Wq = (const float*)d_in[3];
    const float* Wk = (const float*)d_in[4];
    float* Out = (float*)d_out;

    cudaFuncSetAttribute(fmap_kernel,
                         cudaFuncAttributeMaxDynamicSharedMemorySize, FM_SMEM);
    cudaFuncSetAttribute(out_kernel,
                         cudaFuncAttributeMaxDynamicSharedMemorySize, OUT_SMEM);

    fmap_kernel<<<dim3(L_ / 128, BH_), 256, FM_SMEM>>>(K, V, Wk);
    scan_kernel<<<dim3(17, BH_), 256>>>();
    out_kernel<<<dim3(NC_, BH_), 256, OUT_SMEM>>>(Q, Wq, V, Out);
}

// round 16
// speedup vs baseline: 1.0184x; 1.0184x over previous
#include <cuda_runtime.h>
#include <cstdint>

#define B_ 2
#define H_ 16
#define L_ 2048
#define D_ 64
#define BH_ (B_*H_)
#define NC_ 32            // chunks per bh (chunk = 64 rows)
#define EPS_ 1e-6f

typedef unsigned long long u64;

// Scratch (device globals; allocation-free rule).
__device__ float g_kf[(size_t)BH_ * L_ * D_];            // relu(K @ Wk)
__device__ float g_kv[(size_t)BH_ * NC_ * D_ * D_];      // per-chunk Kf^T V
__device__ float g_state[(size_t)BH_ * NC_ * D_ * D_];   // exclusive prefix of g_kv
__device__ float g_ks[(size_t)BH_ * NC_ * D_];           // per-chunk sum of kf
__device__ float g_zs[(size_t)BH_ * NC_ * D_];           // exclusive prefix of g_ks

// ---- packed f32x2 helpers (Blackwell FFMA2 path; used in fmap) ----
__device__ __forceinline__ u64 pk2(float lo, float hi) {
    u64 r; asm("mov.b64 %0, {%1, %2};" : "=l"(r) : "f"(lo), "f"(hi)); return r;
}
__device__ __forceinline__ u64 dup2(float x) {
    u64 r; asm("mov.b64 %0, {%1, %1};" : "=l"(r) : "f"(x)); return r;
}
__device__ __forceinline__ void fma2(u64& d, u64 a, u64 b) {
    asm("fma.rn.f32x2 %0, %1, %2, %0;" : "+l"(d) : "l"(a), "l"(b));
}
__device__ __forceinline__ float2 up2(u64 v) {
    float lo, hi; asm("mov.b64 {%0, %1}, %2;" : "=f"(lo), "=f"(hi) : "l"(v));
    return make_float2(lo, hi);
}

// ===========================================================================
// Key-path feature map + per-chunk KV/ksum.  128 rows per block.
// Grid (L/128, BH); 256 threads; 8x4 micro-tiles; FFMA2; main GEMM unroll 8.
// ===========================================================================
#define FM_SMEM 69632

__global__ __launch_bounds__(256)
void fmap_kernel(const float* __restrict__ K, const float* __restrict__ V,
                 const float* __restrict__ Wk)
{
    extern __shared__ float sm[];
    float (*XT)[136] = (float(*)[136])sm;
    float (*Ws)[68]  = (float(*)[68])(sm + 64 * 136);

    const int tile = blockIdx.x, bh = blockIdx.y;
    const int h = bh & (H_ - 1);

    const int tid = threadIdx.x;
    const int row4 = tid >> 2, d0 = (tid & 3) << 4;
    const size_t rowbase = (size_t)bh * L_ + (size_t)tile * 128;

    #pragma unroll
    for (int rr = 0; rr < 128; rr += 64) {
        const float* src = K + (rowbase + rr + row4) * D_ + d0;
        #pragma unroll
        for (int i = 0; i < 4; i++) {
            float4 v = *(const float4*)(src + i * 4);
            XT[d0 + i*4 + 0][rr + row4] = v.x; XT[d0 + i*4 + 1][rr + row4] = v.y;
            XT[d0 + i*4 + 2][rr + row4] = v.z; XT[d0 + i*4 + 3][rr + row4] = v.w;
        }
    }
    {
        const float* wsrc = Wk + (size_t)h * D_ * D_ + (size_t)row4 * D_ + d0;
        #pragma unroll
        for (int i = 0; i < 4; i++)
            *(float4*)&Ws[row4][d0 + i*4] = *(const float4*)(wsrc + i * 4);
    }
    __syncthreads();

    const int ty = tid >> 4, tx = tid & 15;
    u64 acc2[4][4] = {};
    #pragma unroll 8
    for (int d = 0; d < 64; d++) {
        float4 a0 = *(const float4*)&XT[d][ty * 8];
        float4 a1 = *(const float4*)&XT[d][ty * 8 + 4];
        float4 b  = *(const float4*)&Ws[d][tx * 4];
        u64 pa[4] = {pk2(a0.x, a0.y), pk2(a0.z, a0.w),
                     pk2(a1.x, a1.y), pk2(a1.z, a1.w)};
        u64 db[4] = {dup2(b.x), dup2(b.y), dup2(b.z), dup2(b.w)};
        #pragma unroll
        for (int p = 0; p < 4; p++)
            #pragma unroll
            for (int c = 0; c < 4; c++)
                fma2(acc2[p][c], pa[p], db[c]);
    }
    float acc[8][4];
    #pragma unroll
    for (int p = 0; p < 4; p++)
        #pragma unroll
        for (int c = 0; c < 4; c++) {
            float2 v = up2(acc2[p][c]);
            acc[2*p + 0][c] = fmaxf(v.x, 0.f);
            acc[2*p + 1][c] = fmaxf(v.y, 0.f);
        }

    {
        float* dst = g_kf + (rowbase + ty * 8) * D_ + tx * 4;
        #pragma unroll
        for (int r = 0; r < 8; r++)
            *(float4*)(dst + (size_t)r * D_) =
                make_float4(acc[r][0], acc[r][1], acc[r][2], acc[r][3]);
    }

    __syncthreads();
    float (*Ks)[68]  = (float(*)[68])sm;
    float (*Vs2)[68] = (float(*)[68])(sm + 128 * 68);

    #pragma unroll
    for (int r = 0; r < 8; r++)
        *(float4*)&Ks[ty * 8 + r][tx * 4] =
            make_float4(acc[r][0], acc[r][1], acc[r][2], acc[r][3]);
    #pragma unroll
    for (int rr = 0; rr < 128; rr += 64) {
        const float* vs = V + (rowbase + rr + row4) * D_ + d0;
        #pragma unroll
        for (int i = 0; i < 4; i++)
            *(float4*)&Vs2[rr + row4][d0 + i*4] = *(const float4*)(vs + i * 4);
    }
    __syncthreads();

    const int chunk = ty >> 3, tyc = ty & 7;
    const int nbase = chunk * 64;
    u64 kv2[4][4] = {};
    #pragma unroll 4
    for (int n = 0; n < 64; n++) {
        float4 a0 = *(const float4*)&Ks[nbase + n][tyc * 8];
        float4 a1 = *(const float4*)&Ks[nbase + n][tyc * 8 + 4];
        float4 b  = *(const float4*)&Vs2[nbase + n][tx * 4];
        u64 pa[4] = {pk2(a0.x, a0.y), pk2(a0.z, a0.w),
                     pk2(a1.x, a1.y), pk2(a1.z, a1.w)};
        u64 db[4] = {dup2(b.x), dup2(b.y), dup2(b.z), dup2(b.w)};
        #pragma unroll
        for (int p = 0; p < 4; p++)
            #pragma unroll
            for (int c = 0; c < 4; c++)
                fma2(kv2[p][c], pa[p], db[c]);
    }
    {
        float* kvdst = g_kv + ((size_t)(bh * NC_ + tile * 2 + chunk) * D_
                               + tyc * 8) * D_ + tx * 4;
        #pragma unroll
        for (int p = 0; p < 4; p++) {
            float2 v0 = up2(kv2[p][0]), v1 = up2(kv2[p][1]);
            float2 v2 = up2(kv2[p][2]), v3 = up2(kv2[p][3]);
            *(float4*)(kvdst + (size_t)(2*p) * D_)     = make_float4(v0.x, v1.x, v2.x, v3.x);
            *(float4*)(kvdst + (size_t)(2*p + 1) * D_) = make_float4(v0.y, v1.y, v2.y, v3.y);
        }
    }
    if (tid < 128) {
        const int c2 = tid >> 6, d = tid & 63;
        float s = 0.f;
        #pragma unroll 8
        for (int n = 0; n < 64; n++) s += Ks[c2 * 64 + n][d];
        g_ks[(size_t)(bh * NC_ + tile * 2 + c2) * D_ + d] = s;
    }
}

// ===========================================================================
// Exclusive prefix scan over chunks (per bh, per element).
// ===========================================================================
__global__ __launch_bounds__(256)
void scan_kernel()
{
    const int g = blockIdx.x, bh = blockIdx.y, tid = threadIdx.x;
    if (g < 16) {
        const int e = g * 256 + tid;
        float acc = 0.f;
        #pragma unroll
        for (int c = 0; c < NC_; c++) {
            const size_t idx = (size_t)(bh * NC_ + c) * (D_ * D_) + e;
            g_state[idx] = acc;
            acc += g_kv[idx];
        }
    } else if (tid < 64) {
        float acc = 0.f;
        #pragma unroll
        for (int c = 0; c < NC_; c++) {
            const size_t idx = (size_t)(bh * NC_ + c) * D_ + tid;
            g_zs[idx] = acc;
            acc += g_ks[idx];
        }
    }
}

// ===========================================================================
// Per-chunk output, 3 smem buffers, FUSED GEMM1+GEMM3 (best configuration).
// ===========================================================================
#define OUT_SMEM ((3 * 64 * 68 + 192) * 4)   // 52992 B

__global__ __launch_bounds__(256, 4)
void out_kernel(const float* __restrict__ Q, const float* __restrict__ Wq,
                const float* __restrict__ V, float* __restrict__ Out)
{
    extern __shared__ float sm[];
    float (*bufA)[68] = (float(*)[68])(sm);                 // Wq -> state -> V
    float (*bufB)[68] = (float(*)[68])(sm + 1 * 64 * 68);   // Q^T -> qT[e][m]
    float (*bufC)[68] = (float(*)[68])(sm + 2 * 64 * 68);   // kT[e][n] -> St[n][m]
    float* rowsum     = sm + 3 * 64 * 68;                   // [64]
    float* qz         = rowsum + 64;                        // [64]
    float* zs         = qz + 64;                            // [64]

    const int c = blockIdx.x, bh = blockIdx.y;
    const int h = bh & (H_ - 1);
    const int tid = threadIdx.x;
    const int ty = tid >> 4, tx = tid & 15;
    const size_t rowbase = (size_t)bh * L_ + (size_t)c * 64;
    const size_t chunk = (size_t)(bh * NC_ + c);
    const int row = tid >> 2, d0 = (tid & 3) << 4;

    // ---- 1: load Wq->A, Q^T->B, kf^T->C ----
    {
        const float* ws = Wq + (size_t)h * D_ * D_ + (size_t)row * D_ + d0;
        const float* qs = Q + (rowbase + row) * D_ + d0;
        const float* ks = g_kf + (rowbase + row) * D_ + d0;
        #pragma unroll
        for (int i = 0; i < 4; i++) {
            *(float4*)&bufA[row][d0 + i*4] = *(const float4*)(ws + i * 4);
            float4 q4 = *(const float4*)(qs + i * 4);
            bufB[d0 + i*4 + 0][row] = q4.x; bufB[d0 + i*4 + 1][row] = q4.y;
            bufB[d0 + i*4 + 2][row] = q4.z; bufB[d0 + i*4 + 3][row] = q4.w;
            float4 k4 = *(const float4*)(ks + i * 4);
            bufC[d0 + i*4 + 0][row] = k4.x; bufC[d0 + i*4 + 1][row] = k4.y;
            bufC[d0 + i*4 + 2][row] = k4.z; bufC[d0 + i*4 + 3][row] = k4.w;
        }
        if (tid < 64) zs[tid] = g_zs[chunk * D_ + tid];
    }
    __syncthreads();

    // ---- 2: GEMM0 qf^T = relu(Wq^T Q^T) ----
    float qt[4][4] = {};
    #pragma unroll 8
    for (int d = 0; d < 64; d++) {
        float4 a = *(const float4*)&bufA[d][ty * 4];
        float4 b = *(const float4*)&bufB[d][tx * 4];
        float av[4] = {a.x, a.y, a.z, a.w};
        float bv[4] = {b.x, b.y, b.z, b.w};
        #pragma unroll
        for (int r = 0; r < 4; r++)
            #pragma unroll
            for (int cc = 0; cc < 4; cc++)
                qt[r][cc] = fmaf(av[r], bv[cc], qt[r][cc]);
    }
    #pragma unroll
    for (int r = 0; r < 4; r++)
        #pragma unroll
        for (int cc = 0; cc < 4; cc++)
            qt[r][cc] = fmaxf(qt[r][cc], 0.f);
    __syncthreads();   // A/B reads done

    // ---- 3: qT -> B ; state -> A ----
    float (*qT)[68] = bufB;    // qT[e][m]
    #pragma unroll
    for (int r = 0; r < 4; r++)
        *(float4*)&qT[ty * 4 + r][tx * 4] =
            make_float4(qt[r][0], qt[r][1], qt[r][2], qt[r][3]);
    float (*Sts)[68] = bufA;   // state[d][e]
    {
        const float* ss = g_state + (chunk * D_ + row) * D_ + d0;
        #pragma unroll
        for (int i = 0; i < 4; i++)
            *(float4*)&Sts[row][d0 + i*4] = *(const float4*)(ss + i * 4);
    }
    __syncthreads();

    // ---- 4: FUSED GEMM1+GEMM3: shared a = qT[d][ty*4] ----
    float s[4][4] = {};
    float o[4][4] = {};
    #pragma unroll 4
    for (int d = 0; d < 64; d++) {
        float4 a  = *(const float4*)&qT[d][ty * 4];
        float4 b1 = *(const float4*)&bufC[d][tx * 4];
        float4 b2 = *(const float4*)&Sts[d][tx * 4];
        float av[4]  = {a.x, a.y, a.z, a.w};
        float bv1[4] = {b1.x, b1.y, b1.z, b1.w};
        float bv2[4] = {b2.x, b2.y, b2.z, b2.w};
        #pragma unroll
        for (int r = 0; r < 4; r++)
            #pragma unroll
            for (int cc = 0; cc < 4; cc++) {
                s[r][cc] = fmaf(av[r], bv1[cc], s[r][cc]);
                o[r][cc] = fmaf(av[r], bv2[cc], o[r][cc]);
            }
    }
    #pragma unroll
    for (int r = 0; r < 4; r++)
        #pragma unroll
        for (int cc = 0; cc < 4; cc++)
            if (tx * 4 + cc > ty * 4 + r) s[r][cc] = 0.f;   // causal within chunk

    #pragma unroll
    for (int r = 0; r < 4; r++) {
        float p = (s[r][0] + s[r][1]) + (s[r][2] + s[r][3]);
        p += __shfl_xor_sync(0xffffffffu, p, 1);
        p += __shfl_xor_sync(0xffffffffu, p, 2);
        p += __shfl_xor_sync(0xffffffffu, p, 4);
        p += __shfl_xor_sync(0xffffffffu, p, 8);
        if (tx == 0) rowsum[ty * 4 + r] = p;
    }
    if (tid < 64) {   // qz[m] = qf[m] . z_prev
        float acc = 0.f;
        #pragma unroll 8
        for (int d = 0; d < 64; d++) acc = fmaf(qT[d][tid], zs[d], acc);
        qz[tid] = acc;
    }
    __syncthreads();   // C (kT) + A (state) reads done

    // ---- 5: S^T -> C ; V -> A ----
    float (*St)[68] = bufC;   // St[n][m]
    #pragma unroll
    for (int cc = 0; cc < 4; cc++)
        *(float4*)&St[tx * 4 + cc][ty * 4] =
            make_float4(s[0][cc], s[1][cc], s[2][cc], s[3][cc]);
    float (*Vs)[68] = bufA;   // V[n][dv]
    {
        const float* vs = V + (rowbase + row) * D_ + d0;
        #pragma unroll
        for (int i = 0; i < 4; i++)
            *(float4*)&Vs[row][d0 + i*4] = *(const float4*)(vs + i * 4);
    }
    __syncthreads();

    // ---- 6: GEMM2 O += S @ V (causal bound: warp w rows <= 8w+7 -> n < 8w+8)
    const int nmax = ((tid >> 5) << 3) + 8;
    #pragma unroll 4
    for (int n = 0; n < nmax; n++) {
        float4 a = *(const float4*)&St[n][ty * 4];
        float4 b = *(const float4*)&Vs[n][tx * 4];
        float av[4] = {a.x, a.y, a.z, a.w};
        float bv[4] = {b.x, b.y, b.z, b.w};
        #pragma unroll
        for (int r = 0; r < 4; r++)
            #pragma unroll
            for (int cc = 0; cc < 4; cc++)
                o[r][cc] = fmaf(av[r], bv[cc], o[r][cc]);
    }

    float* dst = Out + (rowbase + ty * 4) * D_ + tx * 4;
    #pragma unroll
    for (int r = 0; r < 4; r++) {
        const float inv = 1.0f / (rowsum[ty * 4 + r] + qz[ty * 4 + r] + EPS_);
        *(float4*)(dst + (size_t)r * D_) =
            make_float4(o[r][0] * inv, o[r][1] * inv, o[r][2] * inv, o[r][3] * inv);
    }
}

// ===========================================================================
extern "C" void kernel_launch(void* const* d_in, const int* in_sizes, int n_in,
                              void* d_out, int out_size)
{
    (void)in_sizes; (void)n_in; (void)out_size;
    const float* Q  = (const float*)d_in[0];
    const float* K  = (const float*)d_in[1];
    const float* V  = (const float*)d_in[2];
    const float* Wq = (const float*)d_in[3];
    const float* Wk = (const float*)d_in[4];
    float* Out = (float*)d_out;

    cudaFuncSetAttribute(fmap_kernel,
                         cudaFuncAttributeMaxDynamicSharedMemorySize, FM_SMEM);
    cudaFuncSetAttribute(out_kernel,
                         cudaFuncAttributeMaxDynamicSharedMemorySize, OUT_SMEM);

    fmap_kernel<<<dim3(L_ / 128, BH_), 256, FM_SMEM>>>(K, V, Wk);
    scan_kernel<<<dim3(17, BH_), 256>>>();
    out_kernel<<<dim3(NC_, BH_), 256, OUT_SMEM>>>(Q, Wq, V, Out);
}

// round 17
// speedup vs baseline: 1.0187x; 1.0003x over previous
#include <cuda_runtime.h>
#include <cstdint>

#define B_ 2
#define H_ 16
#define L_ 2048
#define D_ 64
#define BH_ (B_*H_)
#define NC_ 32            // chunks per bh (chunk = 64 rows)
#define EPS_ 1e-6f

typedef unsigned long long u64;

// Scratch (device globals; allocation-free rule).
__device__ float g_kf[(size_t)BH_ * L_ * D_];            // relu(K @ Wk)
__device__ float g_kv[(size_t)BH_ * NC_ * D_ * D_];      // per-chunk Kf^T V
__device__ float g_state[(size_t)BH_ * NC_ * D_ * D_];   // exclusive prefix of g_kv
__device__ float g_ks[(size_t)BH_ * NC_ * D_];           // per-chunk sum of kf
__device__ float g_zs[(size_t)BH_ * NC_ * D_];           // exclusive prefix of g_ks

// ---- packed f32x2 helpers (Blackwell FFMA2 path; used in fmap) ----
__device__ __forceinline__ u64 pk2(float lo, float hi) {
    u64 r; asm("mov.b64 %0, {%1, %2};" : "=l"(r) : "f"(lo), "f"(hi)); return r;
}
__device__ __forceinline__ u64 dup2(float x) {
    u64 r; asm("mov.b64 %0, {%1, %1};" : "=l"(r) : "f"(x)); return r;
}
__device__ __forceinline__ void fma2(u64& d, u64 a, u64 b) {
    asm("fma.rn.f32x2 %0, %1, %2, %0;" : "+l"(d) : "l"(a), "l"(b));
}
__device__ __forceinline__ float2 up2(u64 v) {
    float lo, hi; asm("mov.b64 {%0, %1}, %2;" : "=f"(lo), "=f"(hi) : "l"(v));
    return make_float2(lo, hi);
}

__device__ __forceinline__ void grid_dep_sync() {
#if defined(__CUDA_ARCH__) && __CUDA_ARCH__ >= 900
    cudaGridDependencySynchronize();
#endif
}

// ===========================================================================
// Key-path feature map + per-chunk KV/ksum.  128 rows per block.
// Grid (L/128, BH); 256 threads; 8x4 micro-tiles; FFMA2; main GEMM unroll 8.
// (round-13/16 exact, best measured)
// ===========================================================================
#define FM_SMEM 69632

__global__ __launch_bounds__(256)
void fmap_kernel(const float* __restrict__ K, const float* __restrict__ V,
                 const float* __restrict__ Wk)
{
    extern __shared__ float sm[];
    float (*XT)[136] = (float(*)[136])sm;
    float (*Ws)[68]  = (float(*)[68])(sm + 64 * 136);

    const int tile = blockIdx.x, bh = blockIdx.y;
    const int h = bh & (H_ - 1);

    const int tid = threadIdx.x;
    const int row4 = tid >> 2, d0 = (tid & 3) << 4;
    const size_t rowbase = (size_t)bh * L_ + (size_t)tile * 128;

    #pragma unroll
    for (int rr = 0; rr < 128; rr += 64) {
        const float* src = K + (rowbase + rr + row4) * D_ + d0;
        #pragma unroll
        for (int i = 0; i < 4; i++) {
            float4 v = *(const float4*)(src + i * 4);
            XT[d0 + i*4 + 0][rr + row4] = v.x; XT[d0 + i*4 + 1][rr + row4] = v.y;
            XT[d0 + i*4 + 2][rr + row4] = v.z; XT[d0 + i*4 + 3][rr + row4] = v.w;
        }
    }
    {
        const float* wsrc = Wk + (size_t)h * D_ * D_ + (size_t)row4 * D_ + d0;
        #pragma unroll
        for (int i = 0; i < 4; i++)
            *(float4*)&Ws[row4][d0 + i*4] = *(const float4*)(wsrc + i * 4);
    }
    __syncthreads();

    const int ty = tid >> 4, tx = tid & 15;
    u64 acc2[4][4] = {};
    #pragma unroll 8
    for (int d = 0; d < 64; d++) {
        float4 a0 = *(const float4*)&XT[d][ty * 8];
        float4 a1 = *(const float4*)&XT[d][ty * 8 + 4];
        float4 b  = *(const float4*)&Ws[d][tx * 4];
        u64 pa[4] = {pk2(a0.x, a0.y), pk2(a0.z, a0.w),
                     pk2(a1.x, a1.y), pk2(a1.z, a1.w)};
        u64 db[4] = {dup2(b.x), dup2(b.y), dup2(b.z), dup2(b.w)};
        #pragma unroll
        for (int p = 0; p < 4; p++)
            #pragma unroll
            for (int c = 0; c < 4; c++)
                fma2(acc2[p][c], pa[p], db[c]);
    }
    float acc[8][4];
    #pragma unroll
    for (int p = 0; p < 4; p++)
        #pragma unroll
        for (int c = 0; c < 4; c++) {
            float2 v = up2(acc2[p][c]);
            acc[2*p + 0][c] = fmaxf(v.x, 0.f);
            acc[2*p + 1][c] = fmaxf(v.y, 0.f);
        }

    {
        float* dst = g_kf + (rowbase + ty * 8) * D_ + tx * 4;
        #pragma unroll
        for (int r = 0; r < 8; r++)
            *(float4*)(dst + (size_t)r * D_) =
                make_float4(acc[r][0], acc[r][1], acc[r][2], acc[r][3]);
    }

    __syncthreads();
    float (*Ks)[68]  = (float(*)[68])sm;
    float (*Vs2)[68] = (float(*)[68])(sm + 128 * 68);

    #pragma unroll
    for (int r = 0; r < 8; r++)
        *(float4*)&Ks[ty * 8 + r][tx * 4] =
            make_float4(acc[r][0], acc[r][1], acc[r][2], acc[r][3]);
    #pragma unroll
    for (int rr = 0; rr < 128; rr += 64) {
        const float* vs = V + (rowbase + rr + row4) * D_ + d0;
        #pragma unroll
        for (int i = 0; i < 4; i++)
            *(float4*)&Vs2[rr + row4][d0 + i*4] = *(const float4*)(vs + i * 4);
    }
    __syncthreads();

    const int chunk = ty >> 3, tyc = ty & 7;
    const int nbase = chunk * 64;
    u64 kv2[4][4] = {};
    #pragma unroll 4
    for (int n = 0; n < 64; n++) {
        float4 a0 = *(const float4*)&Ks[nbase + n][tyc * 8];
        float4 a1 = *(const float4*)&Ks[nbase + n][tyc * 8 + 4];
        float4 b  = *(const float4*)&Vs2[nbase + n][tx * 4];
        u64 pa[4] = {pk2(a0.x, a0.y), pk2(a0.z, a0.w),
                     pk2(a1.x, a1.y), pk2(a1.z, a1.w)};
        u64 db[4] = {dup2(b.x), dup2(b.y), dup2(b.z), dup2(b.w)};
        #pragma unroll
        for (int p = 0; p < 4; p++)
            #pragma unroll
            for (int c = 0; c < 4; c++)
                fma2(kv2[p][c], pa[p], db[c]);
    }
    {
        float* kvdst = g_kv + ((size_t)(bh * NC_ + tile * 2 + chunk) * D_
                               + tyc * 8) * D_ + tx * 4;
        #pragma unroll
        for (int p = 0; p < 4; p++) {
            float2 v0 = up2(kv2[p][0]), v1 = up2(kv2[p][1]);
            float2 v2 = up2(kv2[p][2]), v3 = up2(kv2[p][3]);
            *(float4*)(kvdst + (size_t)(2*p) * D_)     = make_float4(v0.x, v1.x, v2.x, v3.x);
            *(float4*)(kvdst + (size_t)(2*p + 1) * D_) = make_float4(v0.y, v1.y, v2.y, v3.y);
        }
    }
    if (tid < 128) {
        const int c2 = tid >> 6, d = tid & 63;
        float s = 0.f;
        #pragma unroll 8
        for (int n = 0; n < 64; n++) s += Ks[c2 * 64 + n][d];
        g_ks[(size_t)(bh * NC_ + tile * 2 + c2) * D_ + d] = s;
    }
}

// ===========================================================================
// Exclusive prefix scan over chunks. PDL secondary: gridDepSync before the
// first g_kv/g_ks read (allows early block launch + setup overlap).
// ===========================================================================
__global__ __launch_bounds__(256)
void scan_kernel()
{
    const int g = blockIdx.x, bh = blockIdx.y, tid = threadIdx.x;
    grid_dep_sync();
    if (g < 16) {
        const int e = g * 256 + tid;
        float acc = 0.f;
        #pragma unroll
        for (int c = 0; c < NC_; c++) {
            const size_t idx = (size_t)(bh * NC_ + c) * (D_ * D_) + e;
            g_state[idx] = acc;
            acc += g_kv[idx];
        }
    } else if (tid < 64) {
        float acc = 0.f;
        #pragma unroll
        for (int c = 0; c < NC_; c++) {
            const size_t idx = (size_t)(bh * NC_ + c) * D_ + tid;
            g_zs[idx] = acc;
            acc += g_ks[idx];
        }
    }
}

// ===========================================================================
// Per-chunk output, 3 smem buffers, FUSED GEMM1+GEMM3. PDL secondary:
// Q/Wq/g_kf loads + GEMM0 run concurrently with scan (their data predates
// scan); gridDepSync guards only the g_zs / g_state reads.
// ===========================================================================
#define OUT_SMEM ((3 * 64 * 68 + 192) * 4)   // 52992 B

__global__ __launch_bounds__(256, 4)
void out_kernel(const float* __restrict__ Q, const float* __restrict__ Wq,
                const float* __restrict__ V, float* __restrict__ Out)
{
    extern __shared__ float sm[];
    float (*bufA)[68] = (float(*)[68])(sm);                 // Wq -> state -> V
    float (*bufB)[68] = (float(*)[68])(sm + 1 * 64 * 68);   // Q^T -> qT[e][m]
    float (*bufC)[68] = (float(*)[68])(sm + 2 * 64 * 68);   // kT[e][n] -> St[n][m]
    float* rowsum     = sm + 3 * 64 * 68;                   // [64]
    float* qz         = rowsum + 64;                        // [64]
    float* zs         = qz + 64;                            // [64]

    const int c = blockIdx.x, bh = blockIdx.y;
    const int h = bh & (H_ - 1);
    const int tid = threadIdx.x;
    const int ty = tid >> 4, tx = tid & 15;
    const size_t rowbase = (size_t)bh * L_ + (size_t)c * 64;
    const size_t chunk = (size_t)(bh * NC_ + c);
    const int row = tid >> 2, d0 = (tid & 3) << 4;

    // ---- 1: load Wq->A, Q^T->B, kf^T->C (all pre-scan data; overlaps scan) ----
    {
        const float* ws = Wq + (size_t)h * D_ * D_ + (size_t)row * D_ + d0;
        const float* qs = Q + (rowbase + row) * D_ + d0;
        const float* ks = g_kf + (rowbase + row) * D_ + d0;
        #pragma unroll
        for (int i = 0; i < 4; i++) {
            *(float4*)&bufA[row][d0 + i*4] = *(const float4*)(ws + i * 4);
            float4 q4 = *(const float4*)(qs + i * 4);
            bufB[d0 + i*4 + 0][row] = q4.x; bufB[d0 + i*4 + 1][row] = q4.y;
            bufB[d0 + i*4 + 2][row] = q4.z; bufB[d0 + i*4 + 3][row] = q4.w;
            float4 k4 = *(const float4*)(ks + i * 4);
            bufC[d0 + i*4 + 0][row] = k4.x; bufC[d0 + i*4 + 1][row] = k4.y;
            bufC[d0 + i*4 + 2][row] = k4.z; bufC[d0 + i*4 + 3][row] = k4.w;
        }
    }

    // Wait for scan's g_zs/g_state before consuming them.
    grid_dep_sync();
    if (tid < 64) zs[tid] = g_zs[chunk * D_ + tid];
    __syncthreads();

    // ---- 2: GEMM0 qf^T = relu(Wq^T Q^T) ----
    float qt[4][4] = {};
    #pragma unroll 8
    for (int d = 0; d < 64; d++) {
        float4 a = *(const float4*)&bufA[d][ty * 4];
        float4 b = *(const float4*)&bufB[d][tx * 4];
        float av[4] = {a.x, a.y, a.z, a.w};
        float bv[4] = {b.x, b.y, b.z, b.w};
        #pragma unroll
        for (int r = 0; r < 4; r++)
            #pragma unroll
            for (int cc = 0; cc < 4; cc++)
                qt[r][cc] = fmaf(av[r], bv[cc], qt[r][cc]);
    }
    #pragma unroll
    for (int r = 0; r < 4; r++)
        #pragma unroll
        for (int cc = 0; cc < 4; cc++)
            qt[r][cc] = fmaxf(qt[r][cc], 0.f);
    __syncthreads();   // A/B reads done

    // ---- 3: qT -> B ; state -> A ----
    float (*qT)[68] = bufB;    // qT[e][m]
    #pragma unroll
    for (int r = 0; r < 4; r++)
        *(float4*)&qT[ty * 4 + r][tx * 4] =
            make_float4(qt[r][0], qt[r][1], qt[r][2], qt[r][3]);
    float (*Sts)[68] = bufA;   // state[d][e]
    {
        const float* ss = g_state + (chunk * D_ + row) * D_ + d0;
        #pragma unroll
        for (int i = 0; i < 4; i++)
            *(float4*)&Sts[row][d0 + i*4] = *(const float4*)(ss + i * 4);
    }
    __syncthreads();

    // ---- 4: FUSED GEMM1+GEMM3: shared a = qT[d][ty*4] ----
    float s[4][4] = {};
    float o[4][4] = {};
    #pragma unroll 4
    for (int d = 0; d < 64; d++) {
        float4 a  = *(const float4*)&qT[d][ty * 4];
        float4 b1 = *(const float4*)&bufC[d][tx * 4];
        float4 b2 = *(const float4*)&Sts[d][tx * 4];
        float av[4]  = {a.x, a.y, a.z, a.w};
        float bv1[4] = {b1.x, b1.y, b1.z, b1.w};
        float bv2[4] = {b2.x, b2.y, b2.z, b2.w};
        #pragma unroll
        for (int r = 0; r < 4; r++)
            #pragma unroll
            for (int cc = 0; cc < 4; cc++) {
                s[r][cc] = fmaf(av[r], bv1[cc], s[r][cc]);
                o[r][cc] = fmaf(av[r], bv2[cc], o[r][cc]);
            }
    }
    #pragma unroll
    for (int r = 0; r < 4; r++)
        #pragma unroll
        for (int cc = 0; cc < 4; cc++)
            if (tx * 4 + cc > ty * 4 + r) s[r][cc] = 0.f;   // causal within chunk

    #pragma unroll
    for (int r = 0; r < 4; r++) {
        float p = (s[r][0] + s[r][1]) + (s[r][2] + s[r][3]);
        p += __shfl_xor_sync(0xffffffffu, p, 1);
        p += __shfl_xor_sync(0xffffffffu, p, 2);
        p += __shfl_xor_sync(0xffffffffu, p, 4);
        p += __shfl_xor_sync(0xffffffffu, p, 8);
        if (tx == 0) rowsum[ty * 4 + r] = p;
    }
    if (tid < 64) {   // qz[m] = qf[m] . z_prev
        float acc = 0.f;
        #pragma unroll 8
        for (int d = 0; d < 64; d++) acc = fmaf(qT[d][tid], zs[d], acc);
        qz[tid] = acc;
    }
    __syncthreads();   // C (kT) + A (state) reads done

    // ---- 5: S^T -> C ; V -> A ----
    float (*St)[68] = bufC;   // St[n][m]
    #pragma unroll
    for (int cc = 0; cc < 4; cc++)
        *(float4*)&St[tx * 4 + cc][ty * 4] =
            make_float4(s[0][cc], s[1][cc], s[2][cc], s[3][cc]);
    float (*Vs)[68] = bufA;   // V[n][dv]
    {
        const float* vs = V + (rowbase + row) * D_ + d0;
        #pragma unroll
        for (int i = 0; i < 4; i++)
            *(float4*)&Vs[row][d0 + i*4] = *(const float4*)(vs + i * 4);
    }
    __syncthreads();

    // ---- 6: GEMM2 O += S @ V (causal bound: warp w rows <= 8w+7 -> n < 8w+8)
    const int nmax = ((tid >> 5) << 3) + 8;
    #pragma unroll 4
    for (int n = 0; n < nmax; n++) {
        float4 a = *(const float4*)&St[n][ty * 4];
        float4 b = *(const float4*)&Vs[n][tx * 4];
        float av[4] = {a.x, a.y, a.z, a.w};
        float bv[4] = {b.x, b.y, b.z, b.w};
        #pragma unroll
        for (int r = 0; r < 4; r++)
            #pragma unroll
            for (int cc = 0; cc < 4; cc++)
                o[r][cc] = fmaf(av[r], bv[cc], o[r][cc]);
    }

    float* dst = Out + (rowbase + ty * 4) * D_ + tx * 4;
    #pragma unroll
    for (int r = 0; r < 4; r++) {
        const float inv = 1.0f / (rowsum[ty * 4 + r] + qz[ty * 4 + r] + EPS_);
        *(float4*)(dst + (size_t)r * D_) =
            make_float4(o[r][0] * inv, o[r][1] * inv, o[r][2] * inv, o[r][3] * inv);
    }
}

// ===========================================================================
extern "C" void kernel_launch(void* const* d_in, const int* in_sizes, int n_in,
                              void* d_out, int out_size)
{
    (void)in_sizes; (void)n_in; (void)out_size;
    const float* Q  = (const float*)d_in[0];
    const float* K  = (const float*)d_in[1];
    const float* V  = (const float*)d_in[2];
    const float* Wq = (const float*)d_in[3];
    const float* Wk = (const float*)d_in[4];
    float* Out = (float*)d_out;

    cudaFuncSetAttribute(fmap_kernel,
                         cudaFuncAttributeMaxDynamicSharedMemorySize, FM_SMEM);
    cudaFuncSetAttribute(out_kernel,
                         cudaFuncAttributeMaxDynamicSharedMemorySize, OUT_SMEM);

    fmap_kernel<<<dim3(L_ / 128, BH_), 256, FM_SMEM>>>(K, V, Wk);

    // PDL attribute: allow each following kernel's blocks to launch before the
    // predecessor completes; device-side cudaGridDependencySynchronize() guards
    // the actual data dependencies.
    cudaLaunchAttribute pdl[1];
    pdl[0].id = cudaLaunchAttributeProgrammaticStreamSerialization;
    pdl[0].val.programmaticStreamSerializationAllowed = 1;

    {
        cudaLaunchConfig_t cfg = {};
        cfg.gridDim = dim3(17, BH_);
        cfg.blockDim = dim3(256);
        cfg.dynamicSmemBytes = 0;
        cfg.stream = 0;
        cfg.attrs = pdl;
        cfg.numAttrs = 1;
        cudaLaunchKernelEx(&cfg, scan_kernel);
    }
    {
        cudaLaunchConfig_t cfg = {};
        cfg.gridDim = dim3(NC_, BH_);
        cfg.blockDim = dim3(256);
        cfg.dynamicSmemBytes = OUT_SMEM;
        cfg.stream = 0;
        cfg.attrs = pdl;
        cfg.numAttrs = 1;
        cudaLaunchKernelEx(&cfg, out_kernel, Q, Wq, V, Out);
    }
}